// round 3
// baseline (speedup 1.0000x reference)
#include <cuda_runtime.h>

#define D_IN  256
#define H_DIM 4096
#define D_OUT 256
#define MAXB  32768

#define BM 64
#define BN 128
#define BK 32
#define WS_PITCH (BN + 4)   // 132 floats: 16B-aligned rows, conflict-free compute reads

// Scratch (no allocations allowed anywhere)
__device__ float g_GT[H_DIM * D_OUT];   // grossberg transposed: [H, D_OUT]
__device__ float g_w2[H_DIM];           // ||w_h||^2, sequential fp32 (bit-replicates reference reduce)
__device__ float g_x2[MAXB];            // ||x_b||^2, sequential fp32
__device__ int   g_win[MAXB];           // winner index per row

// ---------------------------------------------------------------------------
// w2[h] = sequential fp32 sum of squares, k ascending, mul rounded then add.
// One thread per h. (VALIDATED bit-exact vs reference — do not change order.)
// ---------------------------------------------------------------------------
__global__ void w2_kernel(const float* __restrict__ Wk) {
    int h = blockIdx.x * blockDim.x + threadIdx.x;
    if (h >= H_DIM) return;
    const float* row = Wk + h * D_IN;
    float acc = 0.0f;
    for (int k = 0; k < D_IN; k++)
        acc = __fadd_rn(acc, __fmul_rn(row[k], row[k]));
    g_w2[h] = acc;
}

// x2[b] = sequential fp32 sum of squares. One thread per row. (VALIDATED.)
__global__ void x2_kernel(const float* __restrict__ x, int B) {
    int b = blockIdx.x * blockDim.x + threadIdx.x;
    if (b >= B) return;
    const float* row = x + b * D_IN;
    float acc = 0.0f;
    for (int k = 0; k < D_IN; k++)
        acc = __fadd_rn(acc, __fmul_rn(row[k], row[k]));
    g_x2[b] = acc;
}

// ---------------------------------------------------------------------------
// Transpose G [D_OUT, H] -> GT [H, D_OUT] so the per-row gather is coalesced.
// ---------------------------------------------------------------------------
__global__ void transpose_kernel(const float* __restrict__ G) {
    __shared__ float tile[32][33];
    int h0 = blockIdx.x * 32;
    int d0 = blockIdx.y * 32;
    int tx = threadIdx.x, ty = threadIdx.y;
    #pragma unroll
    for (int j = 0; j < 4; j++)
        tile[ty + j * 8][tx] = G[(d0 + ty + j * 8) * H_DIM + h0 + tx];
    __syncthreads();
    #pragma unroll
    for (int j = 0; j < 4; j++)
        g_GT[(h0 + ty + j * 8) * D_OUT + d0 + tx] = tile[tx][ty + j * 8];
}

// ---------------------------------------------------------------------------
// Fused distance-GEMM + argmin. (VALIDATED bit-exact — accumulation order is
// load-bearing: single accumulator per element, __fmaf_rn, k strictly
// ascending 0..255; score tree uncontracted via _rn intrinsics.)
// ---------------------------------------------------------------------------
__global__ void __launch_bounds__(256) argmin_kernel(
    const float* __restrict__ x, const float* __restrict__ Wk)
{
    __shared__ float xs[BM][BK];            // 8 KB
    __shared__ float ws[BK][WS_PITCH];      // ~16.5 KB, [k][n] layout

    const int tid = threadIdx.x;
    const int tr = tid >> 5;                // warp id -> row group (8 rows)
    const int lane = tid & 31;              // lane -> col group (4 cols)
    const int rowBase = blockIdx.x * BM;

    float x2r[8];
    #pragma unroll
    for (int r = 0; r < 8; r++) x2r[r] = g_x2[rowBase + tr * 8 + r];

    float bestv[8];
    int   besti[8];
    #pragma unroll
    for (int r = 0; r < 8; r++) { bestv[r] = 3.4e38f; besti[r] = 0; }

    for (int n0 = 0; n0 < H_DIM; n0 += BN) {
        float acc[8][4];
        #pragma unroll
        for (int r = 0; r < 8; r++)
            #pragma unroll
            for (int c = 0; c < 4; c++) acc[r][c] = 0.0f;

        for (int k0 = 0; k0 < D_IN; k0 += BK) {
            // x tile: 64 rows x 32 k = 512 float4, 2 per thread
            #pragma unroll
            for (int i = 0; i < 2; i++) {
                int idx = tid + i * 256;
                int r = idx >> 3;
                int kq = idx & 7;
                float4 v = *(const float4*)&x[(rowBase + r) * D_IN + k0 + kq * 4];
                *(float4*)&xs[r][kq * 4] = v;
            }
            // W tile transposed into ws[k][n]: 128 n x 8 k-quads, 4 per thread
            #pragma unroll
            for (int i = 0; i < 4; i++) {
                int idx = tid + i * 256;
                int n = idx >> 3;
                int kq = idx & 7;
                float4 v = *(const float4*)&Wk[(n0 + n) * D_IN + k0 + kq * 4];
                ws[kq * 4 + 0][n] = v.x;
                ws[kq * 4 + 1][n] = v.y;
                ws[kq * 4 + 2][n] = v.z;
                ws[kq * 4 + 3][n] = v.w;
            }
            __syncthreads();

            #pragma unroll
            for (int k = 0; k < BK; k += 4) {
                float4 a4[8];
                #pragma unroll
                for (int r = 0; r < 8; r++)
                    a4[r] = *(const float4*)&xs[tr * 8 + r][k];   // broadcast
                #pragma unroll
                for (int kk = 0; kk < 4; kk++) {
                    float4 bv = *(const float4*)&ws[k + kk][lane * 4];
                    float b0 = bv.x, b1 = bv.y, b2 = bv.z, b3 = bv.w;
                    #pragma unroll
                    for (int r = 0; r < 8; r++) {
                        float a = (kk == 0) ? a4[r].x : (kk == 1) ? a4[r].y
                                : (kk == 2) ? a4[r].z : a4[r].w;
                        acc[r][0] = __fmaf_rn(a, b0, acc[r][0]);
                        acc[r][1] = __fmaf_rn(a, b1, acc[r][1]);
                        acc[r][2] = __fmaf_rn(a, b2, acc[r][2]);
                        acc[r][3] = __fmaf_rn(a, b3, acc[r][3]);
                    }
                }
            }
            __syncthreads();
        }

        // Reference-exact score + running argmin. Index ascends within a
        // thread's scan -> strict < keeps the lowest index on exact ties.
        float4 wv = *(const float4*)&g_w2[n0 + lane * 4];
        #pragma unroll
        for (int r = 0; r < 8; r++) {
            #pragma unroll
            for (int c = 0; c < 4; c++) {
                float w2c = (c == 0) ? wv.x : (c == 1) ? wv.y : (c == 2) ? wv.z : wv.w;
                float t = __fadd_rn(x2r[r], -__fmul_rn(2.0f, acc[r][c]));
                float s = __fadd_rn(t, w2c);
                int idx = n0 + lane * 4 + c;
                if (s < bestv[r]) { bestv[r] = s; besti[r] = idx; }
            }
        }
    }

    // warp reduction: min with lowest-index tie-break (matches jnp.argmin)
    #pragma unroll
    for (int r = 0; r < 8; r++) {
        float v = bestv[r];
        int   i = besti[r];
        #pragma unroll
        for (int off = 16; off > 0; off >>= 1) {
            float ov = __shfl_down_sync(0xffffffffu, v, off);
            int   oi = __shfl_down_sync(0xffffffffu, i, off);
            if (ov < v || (ov == v && oi < i)) { v = ov; i = oi; }
        }
        if (lane == 0) g_win[rowBase + tr * 8 + r] = i;
    }
}

// ---------------------------------------------------------------------------
// Gather: out[b,:] = GT[win[b],:] (coalesced float4); winner indices written
// as FLOAT at winOffset — the harness's concatenated output buffer is fp32,
// and all indices < 2^24 so the cast is lossless.
// ---------------------------------------------------------------------------
__global__ void gather_kernel(float* __restrict__ out, int B, int writeWin, int winOffset) {
    int idx = blockIdx.x * blockDim.x + threadIdx.x;   // over B * (D_OUT/4)
    if (idx >= B * (D_OUT / 4)) return;
    int b = idx >> 6;           // D_OUT/4 = 64
    int j = idx & 63;
    int w = g_win[b];
    float4 v = *(const float4*)&g_GT[w * D_OUT + j * 4];
    *(float4*)&out[b * D_OUT + j * 4] = v;
    if (writeWin && j == 0) out[winOffset + b] = (float)w;
}

__global__ void win_only_kernel(float* __restrict__ out, int B) {
    int b = blockIdx.x * blockDim.x + threadIdx.x;
    if (b < B) out[b] = (float)g_win[b];
}

// ---------------------------------------------------------------------------
extern "C" void kernel_launch(void* const* d_in, const int* in_sizes, int n_in,
                              void* d_out, int out_size) {
    const float* x  = (const float*)d_in[0];
    const float* Wk = (const float*)d_in[1];
    const float* G  = (const float*)d_in[2];
    float* out = (float*)d_out;
    int B = in_sizes[0] / D_IN;   // 32768

    w2_kernel<<<(H_DIM + 255) / 256, 256>>>(Wk);
    x2_kernel<<<(B + 255) / 256, 256>>>(x, B);
    transpose_kernel<<<dim3(H_DIM / 32, D_OUT / 32), dim3(32, 8)>>>(G);
    argmin_kernel<<<B / BM, 256>>>(x, Wk);

    if (out_size >= B * D_OUT) {
        int writeWin = (out_size >= B * D_OUT + B) ? 1 : 0;
        int total = B * (D_OUT / 4);
        gather_kernel<<<(total + 255) / 256, 256>>>(out, B, writeWin, B * D_OUT);
    } else {
        win_only_kernel<<<(B + 255) / 256, 256>>>(out, B);
    }
}

// round 4
// speedup vs baseline: 2.3899x; 2.3899x over previous
#include <cuda_runtime.h>

#define D_IN  256
#define H_DIM 4096
#define D_OUT 256
#define MAXB  32768

#define MAXC  16          // candidate slots per row
#define DELTA 0.02f       // screen margin; > 2x worst-case tf32 screen error

// ---------------- scratch (no allocations allowed anywhere) ----------------
__device__ float g_GT[H_DIM * D_OUT];    // grossberg transposed [H, D_OUT]
__device__ float g_w2[H_DIM];            // ||w_h||^2 exact sequential fp32
__device__ float g_x2[MAXB];             // ||x_b||^2 exact sequential fp32
__device__ int   g_win[MAXB];            // winner per row
__device__ int   g_cnt[MAXB];            // candidate count per row
__device__ int   g_cand[MAXB][MAXC];     // candidate indices per row

// ---------------- helpers ----------------
__device__ __forceinline__ unsigned f2tf(float f) {
    unsigned r; asm("cvt.rna.tf32.f32 %0, %1;" : "=r"(r) : "f"(f)); return r;
}
// order-preserving float<->uint key for atomicMin on shared
__device__ __forceinline__ unsigned fkey(float f) {
    unsigned u = __float_as_uint(f);
    return (u & 0x80000000u) ? ~u : (u | 0x80000000u);
}
__device__ __forceinline__ float funkey(unsigned k) {
    return __uint_as_float((k & 0x80000000u) ? (k ^ 0x80000000u) : ~k);
}
__device__ __forceinline__ void mma8(float c[4], const unsigned a[4], const unsigned b[2]) {
    asm("mma.sync.aligned.m16n8k8.row.col.f32.tf32.tf32.f32 "
        "{%0,%1,%2,%3},{%4,%5,%6,%7},{%8,%9},{%0,%1,%2,%3};"
        : "+f"(c[0]), "+f"(c[1]), "+f"(c[2]), "+f"(c[3])
        : "r"(a[0]), "r"(a[1]), "r"(a[2]), "r"(a[3]), "r"(b[0]), "r"(b[1]));
}

// ---------------------------------------------------------------------------
// Exact sequential sums of squares (VALIDATED bit-exact — order load-bearing)
// ---------------------------------------------------------------------------
__global__ void w2_kernel(const float* __restrict__ Wk) {
    int h = blockIdx.x * blockDim.x + threadIdx.x;
    if (h >= H_DIM) return;
    const float* row = Wk + h * D_IN;
    float acc = 0.0f;
    for (int k = 0; k < D_IN; k++)
        acc = __fadd_rn(acc, __fmul_rn(row[k], row[k]));
    g_w2[h] = acc;
}
__global__ void x2_kernel(const float* __restrict__ x, int B) {
    int b = blockIdx.x * blockDim.x + threadIdx.x;
    if (b >= B) return;
    const float* row = x + b * D_IN;
    float acc = 0.0f;
    for (int k = 0; k < D_IN; k++)
        acc = __fadd_rn(acc, __fmul_rn(row[k], row[k]));
    g_x2[b] = acc;
}

// ---------------------------------------------------------------------------
// Transpose G [D_OUT, H] -> GT [H, D_OUT] for coalesced gather.
// ---------------------------------------------------------------------------
__global__ void transpose_kernel(const float* __restrict__ G) {
    __shared__ float tile[32][33];
    int h0 = blockIdx.x * 32;
    int d0 = blockIdx.y * 32;
    int tx = threadIdx.x, ty = threadIdx.y;
    #pragma unroll
    for (int j = 0; j < 4; j++)
        tile[ty + j * 8][tx] = G[(d0 + ty + j * 8) * H_DIM + h0 + tx];
    __syncthreads();
    #pragma unroll
    for (int j = 0; j < 4; j++)
        g_GT[(h0 + ty + j * 8) * D_OUT + d0 + tx] = tile[tx][ty + j * 8];
}

// ---------------------------------------------------------------------------
// TF32 tensor-core screen: per-block 128 rows x all 4096 cols.
// score~ = w2[h] - 2*dot~(x,w). Appends any col within DELTA of the block's
// shared running min into a per-row candidate buffer (provable superset of
// the exact argmin under the tf32 error bound).
// ---------------------------------------------------------------------------
#define XS_PITCH 36    // (36r + k) % 32 = (4r+k)%32 -> conflict-free frag loads
#define WS_PITCH2 132  // (132k + n) % 32 = (4k+n)%32 -> conflict-free

__global__ void __launch_bounds__(256, 2) screen_kernel(
    const float* __restrict__ x, const float* __restrict__ Wk)
{
    __shared__ float xs[128][XS_PITCH];     // 18 KB, tf32-rounded x tile [m][k]
    __shared__ float ws[32][WS_PITCH2];     // 16.9 KB, tf32-rounded W tile [k][n]
    __shared__ float w2s[128];
    __shared__ unsigned smin[128];
    __shared__ int cnt_s[128];
    __shared__ int cand_s[128][MAXC];       // 8 KB

    const int tid  = threadIdx.x;
    const int lane = tid & 31, wid = tid >> 5;
    const int wm = wid >> 2, wn = wid & 3;        // 2 x 4 warp grid
    const int gid = lane >> 2, tig = lane & 3;    // mma fragment coords
    const int rowBase = blockIdx.x * 128;

    if (tid < 128) { smin[tid] = 0xFFFFFFFFu; cnt_s[tid] = 0; }
    __syncthreads();

    for (int n0 = 0; n0 < H_DIM; n0 += 128) {
        if (tid < 128) w2s[tid] = g_w2[n0 + tid];   // synced by first k-loop sync

        float acc[4][4][4];
        #pragma unroll
        for (int mt = 0; mt < 4; mt++)
            #pragma unroll
            for (int nt = 0; nt < 4; nt++)
                #pragma unroll
                for (int q = 0; q < 4; q++) acc[mt][nt][q] = 0.0f;

        for (int k0 = 0; k0 < D_IN; k0 += 32) {
            // x tile: 128 rows x 32 k (tf32-round on the way in)
            #pragma unroll
            for (int i = 0; i < 4; i++) {
                int idx = tid + i * 256;
                int r = idx >> 3, kq = idx & 7;
                float4 v = *(const float4*)&x[(rowBase + r) * D_IN + k0 + kq * 4];
                float4 t;
                t.x = __uint_as_float(f2tf(v.x)); t.y = __uint_as_float(f2tf(v.y));
                t.z = __uint_as_float(f2tf(v.z)); t.w = __uint_as_float(f2tf(v.w));
                *(float4*)&xs[r][kq * 4] = t;
            }
            // W tile transposed [k][n]
            #pragma unroll
            for (int i = 0; i < 4; i++) {
                int idx = tid + i * 256;
                int n = idx >> 3, kq = idx & 7;
                float4 v = *(const float4*)&Wk[(n0 + n) * D_IN + k0 + kq * 4];
                ws[kq * 4 + 0][n] = __uint_as_float(f2tf(v.x));
                ws[kq * 4 + 1][n] = __uint_as_float(f2tf(v.y));
                ws[kq * 4 + 2][n] = __uint_as_float(f2tf(v.z));
                ws[kq * 4 + 3][n] = __uint_as_float(f2tf(v.w));
            }
            __syncthreads();

            #pragma unroll
            for (int ks = 0; ks < 4; ks++) {
                const int kk = ks * 8;
                unsigned a[4][4], b[4][2];
                #pragma unroll
                for (int mt = 0; mt < 4; mt++) {
                    int r0 = wm * 64 + mt * 16 + gid;
                    a[mt][0] = __float_as_uint(xs[r0    ][kk + tig]);
                    a[mt][1] = __float_as_uint(xs[r0 + 8][kk + tig]);
                    a[mt][2] = __float_as_uint(xs[r0    ][kk + tig + 4]);
                    a[mt][3] = __float_as_uint(xs[r0 + 8][kk + tig + 4]);
                }
                #pragma unroll
                for (int nt = 0; nt < 4; nt++) {
                    int c0 = wn * 32 + nt * 8 + gid;
                    b[nt][0] = __float_as_uint(ws[kk + tig    ][c0]);
                    b[nt][1] = __float_as_uint(ws[kk + tig + 4][c0]);
                }
                #pragma unroll
                for (int mt = 0; mt < 4; mt++)
                    #pragma unroll
                    for (int nt = 0; nt < 4; nt++)
                        mma8(acc[mt][nt], a[mt], b[nt]);
            }
            __syncthreads();
        }

        // ---- epilogue: scores, shared row-min, candidate append ----
        float w2v[4][2];
        #pragma unroll
        for (int nt = 0; nt < 4; nt++) {
            w2v[nt][0] = w2s[wn * 32 + nt * 8 + 2 * tig];
            w2v[nt][1] = w2s[wn * 32 + nt * 8 + 2 * tig + 1];
        }
        // pass 1: fold this tile into the shared per-row min
        #pragma unroll
        for (int mt = 0; mt < 4; mt++) {
            #pragma unroll
            for (int h = 0; h < 2; h++) {
                int lr = wm * 64 + mt * 16 + gid + h * 8;
                float m8 = 3.4e38f;
                #pragma unroll
                for (int nt = 0; nt < 4; nt++)
                    #pragma unroll
                    for (int p = 0; p < 2; p++) {
                        float s = fmaf(-2.0f, acc[mt][nt][h * 2 + p], w2v[nt][p]);
                        m8 = fminf(m8, s);
                    }
                m8 = fminf(m8, __shfl_xor_sync(0xffffffffu, m8, 1));
                m8 = fminf(m8, __shfl_xor_sync(0xffffffffu, m8, 2));
                if (tig == 0) atomicMin(&smin[lr], fkey(m8));
            }
        }
        __syncthreads();
        // pass 2: append candidates within DELTA of (tile-inclusive) row min
        #pragma unroll
        for (int mt = 0; mt < 4; mt++) {
            #pragma unroll
            for (int h = 0; h < 2; h++) {
                int lr = wm * 64 + mt * 16 + gid + h * 8;
                float thr = funkey(smin[lr]) + DELTA;
                #pragma unroll
                for (int nt = 0; nt < 4; nt++)
                    #pragma unroll
                    for (int p = 0; p < 2; p++) {
                        float s = fmaf(-2.0f, acc[mt][nt][h * 2 + p], w2v[nt][p]);
                        if (s < thr) {
                            int colg = n0 + wn * 32 + nt * 8 + 2 * tig + p;
                            int pos = atomicAdd(&cnt_s[lr], 1);
                            if (pos < MAXC) cand_s[lr][pos] = colg;
                        }
                    }
            }
        }
        __syncthreads();   // protect w2s/smin reads before next tile overwrites
    }

    if (tid < 128) {
        int b = rowBase + tid;
        int c = cnt_s[tid];
        g_cnt[b] = c;
        int cc = c < MAXC ? c : MAXC;
        for (int i = 0; i < cc; i++) g_cand[b][i] = cand_s[tid][i];
    }
}

// ---------------------------------------------------------------------------
// Exact rescore of candidates (bit-exact recipe: sequential k-ascending FMA,
// uncontracted score tree). One warp per row; lexicographic (score,index) min.
// ---------------------------------------------------------------------------
__device__ __forceinline__ float exact_score(
    const float* __restrict__ xsh, const float* __restrict__ wrow,
    float x2v, float w2v)
{
    float acc = 0.0f;
    const float4* w4 = (const float4*)wrow;
    #pragma unroll 4
    for (int k4 = 0; k4 < D_IN / 4; k4++) {
        float4 wv = w4[k4];
        const float* xp = xsh + k4 * 4;
        acc = __fmaf_rn(xp[0], wv.x, acc);
        acc = __fmaf_rn(xp[1], wv.y, acc);
        acc = __fmaf_rn(xp[2], wv.z, acc);
        acc = __fmaf_rn(xp[3], wv.w, acc);
    }
    float t = __fadd_rn(x2v, -__fmul_rn(2.0f, acc));
    return __fadd_rn(t, w2v);
}

__global__ void __launch_bounds__(256) rescore_kernel(
    const float* __restrict__ x, const float* __restrict__ Wk)
{
    __shared__ float xsh[8][D_IN];   // 8 KB, one row per warp
    int wid = threadIdx.x >> 5, lane = threadIdx.x & 31;
    int b = blockIdx.x * 8 + wid;

    // stage x row into shared (64 float4)
    const float4* xr = (const float4*)(x + b * D_IN);
    float4* xd = (float4*)xsh[wid];
    xd[lane] = xr[lane];
    xd[lane + 32] = xr[lane + 32];
    __syncwarp();

    int cnt = g_cnt[b];
    float x2v = g_x2[b];
    float bv = 3.4e38f;
    int   bi = 0x7FFFFFFF;

    if (cnt <= MAXC) {
        if (lane < cnt) {
            int h = g_cand[b][lane];
            bv = exact_score(xsh[wid], Wk + h * D_IN, x2v, g_w2[h]);
            bi = h;
        }
    } else {
        // overflow fallback: exact full scan (rare, deterministic)
        for (int h = lane; h < H_DIM; h += 32) {
            float s = exact_score(xsh[wid], Wk + h * D_IN, x2v, g_w2[h]);
            if (s < bv) { bv = s; bi = h; }   // h ascending per lane
        }
    }
    #pragma unroll
    for (int off = 16; off > 0; off >>= 1) {
        float ov = __shfl_down_sync(0xffffffffu, bv, off);
        int   oi = __shfl_down_sync(0xffffffffu, bi, off);
        if (ov < bv || (ov == bv && oi < bi)) { bv = ov; bi = oi; }
    }
    if (lane == 0) g_win[b] = bi;
}

// ---------------------------------------------------------------------------
// Gather: out[b,:] = GT[win[b],:]; winner index appended as float (lossless).
// ---------------------------------------------------------------------------
__global__ void gather_kernel(float* __restrict__ out, int B, int writeWin, int winOffset) {
    int idx = blockIdx.x * blockDim.x + threadIdx.x;
    if (idx >= B * (D_OUT / 4)) return;
    int b = idx >> 6;
    int j = idx & 63;
    int w = g_win[b];
    float4 v = *(const float4*)&g_GT[w * D_OUT + j * 4];
    *(float4*)&out[b * D_OUT + j * 4] = v;
    if (writeWin && j == 0) out[winOffset + b] = (float)w;
}

__global__ void win_only_kernel(float* __restrict__ out, int B) {
    int b = blockIdx.x * blockDim.x + threadIdx.x;
    if (b < B) out[b] = (float)g_win[b];
}

// ---------------------------------------------------------------------------
extern "C" void kernel_launch(void* const* d_in, const int* in_sizes, int n_in,
                              void* d_out, int out_size) {
    const float* x  = (const float*)d_in[0];
    const float* Wk = (const float*)d_in[1];
    const float* G  = (const float*)d_in[2];
    float* out = (float*)d_out;
    int B = in_sizes[0] / D_IN;   // 32768

    w2_kernel<<<(H_DIM + 255) / 256, 256>>>(Wk);
    x2_kernel<<<(B + 255) / 256, 256>>>(x, B);
    transpose_kernel<<<dim3(H_DIM / 32, D_OUT / 32), dim3(32, 8)>>>(G);
    screen_kernel<<<B / 128, 256>>>(x, Wk);
    rescore_kernel<<<B / 8, 256>>>(x, Wk);

    if (out_size >= B * D_OUT) {
        int writeWin = (out_size >= B * D_OUT + B) ? 1 : 0;
        int total = B * (D_OUT / 4);
        gather_kernel<<<(total + 255) / 256, 256>>>(out, B, writeWin, B * D_OUT);
    } else {
        win_only_kernel<<<(B + 255) / 256, 256>>>(out, B);
    }
}